// round 7
// baseline (speedup 1.0000x reference)
#include <cuda_runtime.h>
#include <math.h>

// LIF cell scan: v = v*sigmoid(decay)*(1-z) + x_t ; z = (v - 0.5 > 0)
// x [B,T,H] f32 -> spikes [B,T,H] f32.  B=512, T=512, H=256.
//
// R7: float4 double-buffered kernel + L2 prefetch stream running PF t-steps
// ahead of the demand loads. Prefetches need no registers, so the DRAM read
// side gets effectively unbounded MLP; demand loads become L2 hits.

#define B_DIM 512
#define T_DIM 512
#define H_DIM 256
#define HQ    (H_DIM / 4)   // 64 float4 per (b,t) row
#define DEPTH 8             // 2*DEPTH = 16 divides T_DIM = 512
#define PF    32            // prefetch distance in t-steps (32KB/row ahead)

__device__ __forceinline__ void l2_prefetch(const void* p) {
    asm volatile("prefetch.global.L2 [%0];" :: "l"(p));
}

__global__ __launch_bounds__(32)
void lif_scan4_kernel(const float4* __restrict__ x,
                      const float4* __restrict__ decay,
                      const float4* __restrict__ v0,
                      const float4* __restrict__ z0,
                      float4* __restrict__ out)
{
    const int b = blockIdx.x >> 1;                        // 0..511
    const int q = ((blockIdx.x & 1) << 5) + threadIdx.x;  // float4 index in row: 0..63

    // sigmoid(decay) once per chain, correctly rounded via fp64
    const float4 dc = decay[q];
    float4 d;
    d.x = (float)(1.0 / (1.0 + exp(-(double)dc.x)));
    d.y = (float)(1.0 / (1.0 + exp(-(double)dc.y)));
    d.z = (float)(1.0 / (1.0 + exp(-(double)dc.z)));
    d.w = (float)(1.0 / (1.0 + exp(-(double)dc.w)));

    const int bh = b * HQ + q;
    float4 v = v0[bh];
    float4 z = z0[bh];

    const size_t base = (size_t)b * T_DIM * HQ + q;
    const float4* __restrict__ xp = x + base;
    float4* __restrict__ op = out + base;

    float4 xa[DEPTH], xb[DEPTH];

    // Warm the prefetch pipe for t = DEPTH..PF before the first demand miss
    // window closes. (Chunk 0 is demand-loaded below; prefetch the next
    // PF-DEPTH steps.)
    #pragma unroll 4
    for (int i = DEPTH; i < PF; i++)
        l2_prefetch(xp + (size_t)i * HQ);

    // Prologue: chunk 0 (t = 0..7)
    #pragma unroll
    for (int i = 0; i < DEPTH; i++)
        xa[i] = __ldcs(xp + (size_t)i * HQ);

    #pragma unroll 1
    for (int t = 0; t < T_DIM; t += 2 * DEPTH) {
        // L2 prefetch PF steps ahead of this iteration's demand loads.
        // Clamped to stay inside the row (addresses always within x).
        #pragma unroll
        for (int i = 0; i < 2 * DEPTH; i++) {
            int tp = t + PF + i;
            if (tp < T_DIM) l2_prefetch(xp + (size_t)tp * HQ);
        }

        // Demand-load chunk B (t+8..t+15) — in range since 16 | 512
        #pragma unroll
        for (int i = 0; i < DEPTH; i++)
            xb[i] = __ldcs(xp + (size_t)(t + DEPTH + i) * HQ);

        // Compute + store chunk A. (1-z) is exactly 0.0f or 1.0f -> rounding
        // matches the reference association exactly.
        #pragma unroll
        for (int i = 0; i < DEPTH; i++) {
            float4 xv = xa[i];
            v.x = v.x * d.x * (1.0f - z.x) + xv.x;
            v.y = v.y * d.y * (1.0f - z.y) + xv.y;
            v.z = v.z * d.z * (1.0f - z.z) + xv.z;
            v.w = v.w * d.w * (1.0f - z.w) + xv.w;
            z.x = (v.x > 0.5f) ? 1.0f : 0.0f;
            z.y = (v.y > 0.5f) ? 1.0f : 0.0f;
            z.z = (v.z > 0.5f) ? 1.0f : 0.0f;
            z.w = (v.w > 0.5f) ? 1.0f : 0.0f;
            __stcs(op + (size_t)(t + i) * HQ, z);
        }

        // Demand-load next chunk A (t+16..t+23), except on the final iteration
        if (t + 2 * DEPTH < T_DIM) {
            #pragma unroll
            for (int i = 0; i < DEPTH; i++)
                xa[i] = __ldcs(xp + (size_t)(t + 2 * DEPTH + i) * HQ);
        }

        // Compute + store chunk B
        #pragma unroll
        for (int i = 0; i < DEPTH; i++) {
            float4 xv = xb[i];
            v.x = v.x * d.x * (1.0f - z.x) + xv.x;
            v.y = v.y * d.y * (1.0f - z.y) + xv.y;
            v.z = v.z * d.z * (1.0f - z.z) + xv.z;
            v.w = v.w * d.w * (1.0f - z.w) + xv.w;
            z.x = (v.x > 0.5f) ? 1.0f : 0.0f;
            z.y = (v.y > 0.5f) ? 1.0f : 0.0f;
            z.z = (v.z > 0.5f) ? 1.0f : 0.0f;
            z.w = (v.w > 0.5f) ? 1.0f : 0.0f;
            __stcs(op + (size_t)(t + DEPTH + i) * HQ, z);
        }
    }
}

extern "C" void kernel_launch(void* const* d_in, const int* in_sizes, int n_in,
                              void* d_out, int out_size)
{
    // Bind inputs BY SIZE (robust to metadata ordering):
    //   x: B*T*H   decay: H   v0,z0: B*H (both zero at runtime; order harmless)
    const float* x = 0;
    const float* decay = 0;
    const float* v0 = 0;
    const float* z0 = 0;

    const long long n_x  = (long long)B_DIM * T_DIM * H_DIM;
    const long long n_bh = (long long)B_DIM * H_DIM;

    for (int i = 0; i < n_in; i++) {
        long long n = in_sizes[i];
        if (n == n_x) {
            x = (const float*)d_in[i];
        } else if (n == H_DIM) {
            decay = (const float*)d_in[i];
        } else if (n == n_bh) {
            if (!v0) v0 = (const float*)d_in[i];
            else     z0 = (const float*)d_in[i];
        }
    }
    if (!x || !decay || !v0 || !z0) return;

    lif_scan4_kernel<<<B_DIM * 2, 32>>>(
        (const float4*)x, (const float4*)decay,
        (const float4*)v0, (const float4*)z0,
        (float4*)d_out);
}

// round 8
// speedup vs baseline: 1.0070x; 1.0070x over previous
#include <cuda_runtime.h>
#include <math.h>

// LIF cell scan: v = v*sigmoid(decay)*(1-z) + x_t ; z = (v - 0.5 > 0)
// x [B,T,H] f32 -> spikes [B,T,H] f32.  B=512, T=512, H=256.
//
// R8: one warp per b-row; each thread owns 8 h-chains (two float4 slots:
// q and q+32 of the 64-float4 row). Per t-step the warp covers the FULL 1KB
// row, so its load and store streams are strictly linear 512KB sweeps —
// one producer per DRAM region, no interleaving. Double-buffered (DEPTH=4)
// + L2 prefetch 32 steps ahead. Arithmetic association identical to the
// rel_err=0 versions.

#define B_DIM 512
#define T_DIM 512
#define H_DIM 256
#define HQ    (H_DIM / 4)   // 64 float4 per (b,t) row
#define DEPTH 4             // 2*DEPTH = 8 divides T_DIM = 512
#define PF    32            // prefetch distance in t-steps

__device__ __forceinline__ void l2_prefetch(const void* p) {
    asm volatile("prefetch.global.L2 [%0];" :: "l"(p));
}

__device__ __forceinline__ float4 lif_step(float4 v, float4 d, float4* z, float4 xv) {
    float4 nv, nz;
    nv.x = v.x * d.x * (1.0f - z->x) + xv.x;
    nv.y = v.y * d.y * (1.0f - z->y) + xv.y;
    nv.z = v.z * d.z * (1.0f - z->z) + xv.z;
    nv.w = v.w * d.w * (1.0f - z->w) + xv.w;
    nz.x = (nv.x > 0.5f) ? 1.0f : 0.0f;
    nz.y = (nv.y > 0.5f) ? 1.0f : 0.0f;
    nz.z = (nv.z > 0.5f) ? 1.0f : 0.0f;
    nz.w = (nv.w > 0.5f) ? 1.0f : 0.0f;
    *z = nz;
    return nv;
}

__global__ __launch_bounds__(32)
void lif_scan8_kernel(const float4* __restrict__ x,
                      const float4* __restrict__ decay,
                      const float4* __restrict__ v0,
                      const float4* __restrict__ z0,
                      float4* __restrict__ out)
{
    const int b = blockIdx.x;       // 0..511 — one warp per batch row
    const int q = threadIdx.x;      // 0..31; thread owns float4 slots q and q+32

    // sigmoid(decay) once per chain, correctly rounded via fp64
    const float4 dc0 = decay[q];
    const float4 dc1 = decay[q + 32];
    float4 d0, d1;
    d0.x = (float)(1.0 / (1.0 + exp(-(double)dc0.x)));
    d0.y = (float)(1.0 / (1.0 + exp(-(double)dc0.y)));
    d0.z = (float)(1.0 / (1.0 + exp(-(double)dc0.z)));
    d0.w = (float)(1.0 / (1.0 + exp(-(double)dc0.w)));
    d1.x = (float)(1.0 / (1.0 + exp(-(double)dc1.x)));
    d1.y = (float)(1.0 / (1.0 + exp(-(double)dc1.y)));
    d1.z = (float)(1.0 / (1.0 + exp(-(double)dc1.z)));
    d1.w = (float)(1.0 / (1.0 + exp(-(double)dc1.w)));

    const int bh = b * HQ + q;
    float4 v_0 = v0[bh];
    float4 v_1 = v0[bh + 32];
    float4 z_0 = z0[bh];
    float4 z_1 = z0[bh + 32];

    const size_t base = (size_t)b * T_DIM * HQ + q;
    const float4* __restrict__ xp = x + base;   // slot q; slot q+32 at +32
    float4* __restrict__ op = out + base;

    float4 xa[DEPTH][2], xb[DEPTH][2];

    // Warm the L2 prefetch pipe for t = DEPTH..PF
    #pragma unroll 4
    for (int i = DEPTH; i < PF; i++) {
        l2_prefetch(xp + (size_t)i * HQ);
        l2_prefetch(xp + (size_t)i * HQ + 32);
    }

    // Prologue: chunk 0 (t = 0..3)
    #pragma unroll
    for (int i = 0; i < DEPTH; i++) {
        xa[i][0] = __ldcs(xp + (size_t)i * HQ);
        xa[i][1] = __ldcs(xp + (size_t)i * HQ + 32);
    }

    #pragma unroll 1
    for (int t = 0; t < T_DIM; t += 2 * DEPTH) {
        // L2 prefetch PF steps ahead (clamped inside the row)
        #pragma unroll
        for (int i = 0; i < 2 * DEPTH; i++) {
            int tp = t + PF + i;
            if (tp < T_DIM) {
                l2_prefetch(xp + (size_t)tp * HQ);
                l2_prefetch(xp + (size_t)tp * HQ + 32);
            }
        }

        // Demand-load chunk B (t+4..t+7) — in range since 8 | 512
        #pragma unroll
        for (int i = 0; i < DEPTH; i++) {
            xb[i][0] = __ldcs(xp + (size_t)(t + DEPTH + i) * HQ);
            xb[i][1] = __ldcs(xp + (size_t)(t + DEPTH + i) * HQ + 32);
        }

        // Compute + store chunk A
        #pragma unroll
        for (int i = 0; i < DEPTH; i++) {
            v_0 = lif_step(v_0, d0, &z_0, xa[i][0]);
            v_1 = lif_step(v_1, d1, &z_1, xa[i][1]);
            __stcs(op + (size_t)(t + i) * HQ, z_0);
            __stcs(op + (size_t)(t + i) * HQ + 32, z_1);
        }

        // Demand-load next chunk A (t+8..t+11), except on the last iteration
        if (t + 2 * DEPTH < T_DIM) {
            #pragma unroll
            for (int i = 0; i < DEPTH; i++) {
                xa[i][0] = __ldcs(xp + (size_t)(t + 2 * DEPTH + i) * HQ);
                xa[i][1] = __ldcs(xp + (size_t)(t + 2 * DEPTH + i) * HQ + 32);
            }
        }

        // Compute + store chunk B
        #pragma unroll
        for (int i = 0; i < DEPTH; i++) {
            v_0 = lif_step(v_0, d0, &z_0, xb[i][0]);
            v_1 = lif_step(v_1, d1, &z_1, xb[i][1]);
            __stcs(op + (size_t)(t + DEPTH + i) * HQ, z_0);
            __stcs(op + (size_t)(t + DEPTH + i) * HQ + 32, z_1);
        }
    }
}

extern "C" void kernel_launch(void* const* d_in, const int* in_sizes, int n_in,
                              void* d_out, int out_size)
{
    // Bind inputs BY SIZE (robust to metadata ordering):
    //   x: B*T*H   decay: H   v0,z0: B*H (both zero at runtime; order harmless)
    const float* x = 0;
    const float* decay = 0;
    const float* v0 = 0;
    const float* z0 = 0;

    const long long n_x  = (long long)B_DIM * T_DIM * H_DIM;
    const long long n_bh = (long long)B_DIM * H_DIM;

    for (int i = 0; i < n_in; i++) {
        long long n = in_sizes[i];
        if (n == n_x) {
            x = (const float*)d_in[i];
        } else if (n == H_DIM) {
            decay = (const float*)d_in[i];
        } else if (n == n_bh) {
            if (!v0) v0 = (const float*)d_in[i];
            else     z0 = (const float*)d_in[i];
        }
    }
    if (!x || !decay || !v0 || !z0) return;

    lif_scan8_kernel<<<B_DIM, 32>>>(
        (const float4*)x, (const float4*)decay,
        (const float4*)v0, (const float4*)z0,
        (float4*)d_out);
}